// round 2
// baseline (speedup 1.0000x reference)
#include <cuda_runtime.h>
#include <cuda_bf16.h>
#include <math.h>

#define N_USER 100000
#define N_ITEM 60000
#define NN     160000      // total nodes
#define NNZ_E  2000000
#define BB     16384
#define DD     64

// ---------------- device scratch (static, allocation-free) ----------------
__device__ float g_ego [(size_t)NN * DD];        // 41 MB
__device__ float g_side[(size_t)NN * DD];        // 41 MB
__device__ float g_alle[(size_t)NN * 4 * DD];    // 164 MB  [node][256]
__device__ int   g_cnt   [NN];
__device__ int   g_off   [NN + 1];
__device__ int   g_cursor[NN];
__device__ int   g_ccol  [NNZ_E];
__device__ float g_cval  [NNZ_E];

// ---------------- init: ego = concat(user,item); alle slot0; zero side/cnt
__global__ void k_init(const float* __restrict__ ue, const float* __restrict__ ie) {
    int idx = blockIdx.x * blockDim.x + threadIdx.x;
    if (idx < NN * DD) {
        int node = idx >> 6;
        int d    = idx & 63;
        float v  = (node < N_USER) ? ue[idx] : ie[idx - N_USER * DD];
        g_ego[idx]  = v;
        g_side[idx] = 0.f;
        g_alle[(size_t)node * 256 + d] = v;
    }
    if (idx < NN) g_cnt[idx] = 0;
}

// ---------------- CSR build ----------------
__global__ void k_hist(const int* __restrict__ rows) {
    int e = blockIdx.x * blockDim.x + threadIdx.x;
    if (e < NNZ_E) atomicAdd(&g_cnt[rows[e]], 1);
}

// single-block exclusive scan over g_cnt -> g_off, g_cursor
__global__ void k_scan() {
    const int CH = (NN + 1023) >> 10;   // 157
    int t = threadIdx.x;
    int b0 = t * CH;
    int b1 = b0 + CH; if (b1 > NN) b1 = NN;
    if (b0 > NN) b0 = NN;

    int s = 0;
    for (int i = b0; i < b1; i++) s += g_cnt[i];

    __shared__ int wsum[32];
    int lane = t & 31, wid = t >> 5;
    int v = s;
    #pragma unroll
    for (int o = 1; o < 32; o <<= 1) {
        int u = __shfl_up_sync(0xffffffffu, v, o);
        if (lane >= o) v += u;
    }
    if (lane == 31) wsum[wid] = v;
    __syncthreads();
    if (wid == 0) {
        int w = wsum[lane];
        #pragma unroll
        for (int o = 1; o < 32; o <<= 1) {
            int u = __shfl_up_sync(0xffffffffu, w, o);
            if (lane >= o) w += u;
        }
        wsum[lane] = w;  // inclusive warp sums
    }
    __syncthreads();
    int excl = v - s + (wid > 0 ? wsum[wid - 1] : 0);
    int off = excl;
    for (int i = b0; i < b1; i++) {
        g_off[i] = off;
        g_cursor[i] = off;
        off += g_cnt[i];
    }
    if (t == 1023) g_off[NN] = off;   // == NNZ_E
}

__global__ void k_fill(const int* __restrict__ rows, const int* __restrict__ cols,
                       const float* __restrict__ vals) {
    int e = blockIdx.x * blockDim.x + threadIdx.x;
    if (e < NNZ_E) {
        int r = rows[e];
        int p = atomicAdd(&g_cursor[r], 1);
        g_ccol[p] = cols[e];
        g_cval[p] = vals[e];
    }
}

// ---------------- SpMM: side[r] = sum_e val*ego[col]; warp per row ----------
__global__ void k_spmm() {
    int w = (blockIdx.x * blockDim.x + threadIdx.x) >> 5;
    if (w >= NN) return;
    int lane = threadIdx.x & 31;
    int s = g_off[w], e = g_off[w + 1];
    float ax = 0.f, ay = 0.f;
    for (int base = s; base < e; base += 32) {
        int idx = base + lane;
        int c = 0; float v = 0.f;
        if (idx < e) { c = g_ccol[idx]; v = g_cval[idx]; }
        int m = e - base; if (m > 32) m = 32;
        for (int j = 0; j < m; j++) {
            int   cc = __shfl_sync(0xffffffffu, c, j);
            float vv = __shfl_sync(0xffffffffu, v, j);
            float2 g = *(const float2*)&g_ego[(size_t)cc * DD + (lane << 1)];
            ax = fmaf(vv, g.x, ax);
            ay = fmaf(vv, g.y, ay);
        }
    }
    float2 o; o.x = ax; o.y = ay;
    *(float2*)&g_side[(size_t)w * DD + (lane << 1)] = o;
}

// ---------------- transform: GEMMs + bias + leaky-relu + normalize + zero side
// thread = (row within 32-row tile, 8-col group). W served from L1 (broadcast).
__global__ void k_transform(const float* __restrict__ Wg, const float* __restrict__ bg,
                            const float* __restrict__ Wb, const float* __restrict__ bb,
                            int layer) {
    __shared__ float sS[32][65];
    __shared__ float sE[32][65];
    int r0 = blockIdx.x * 32;
    int t = threadIdx.x;

    for (int i = t; i < 32 * 64; i += 256) {
        int rr = i >> 6, dd = i & 63;
        sS[rr][dd] = g_side[(size_t)(r0 + rr) * DD + dd];
        sE[rr][dd] = g_ego [(size_t)(r0 + rr) * DD + dd];
    }
    __syncthreads();

    int r  = t >> 3;
    int j0 = (t & 7) << 3;
    const float* wg = Wg + layer * 4096 + j0;
    const float* wb = Wb + layer * 4096 + j0;
    const float* bgp = bg + layer * 64 + j0;
    const float* bbp = bb + layer * 64 + j0;

    float acc[8];
    #pragma unroll
    for (int j = 0; j < 8; j++)
        acc[j] = bgp[j] + bbp[j];

    #pragma unroll 4
    for (int i = 0; i < 64; i++) {
        float si = sS[r][i];
        float bi = sE[r][i] * si;
        float4 g0 = *(const float4*)(wg + i * 64);
        float4 g1 = *(const float4*)(wg + i * 64 + 4);
        float4 h0 = *(const float4*)(wb + i * 64);
        float4 h1 = *(const float4*)(wb + i * 64 + 4);
        acc[0] = fmaf(si, g0.x, fmaf(bi, h0.x, acc[0]));
        acc[1] = fmaf(si, g0.y, fmaf(bi, h0.y, acc[1]));
        acc[2] = fmaf(si, g0.z, fmaf(bi, h0.z, acc[2]));
        acc[3] = fmaf(si, g0.w, fmaf(bi, h0.w, acc[3]));
        acc[4] = fmaf(si, g1.x, fmaf(bi, h1.x, acc[4]));
        acc[5] = fmaf(si, g1.y, fmaf(bi, h1.y, acc[5]));
        acc[6] = fmaf(si, g1.z, fmaf(bi, h1.z, acc[6]));
        acc[7] = fmaf(si, g1.w, fmaf(bi, h1.w, acc[7]));
    }

    float ss = 0.f;
    #pragma unroll
    for (int j = 0; j < 8; j++) {
        float x = acc[j];
        x = (x > 0.f) ? x : 0.2f * x;   // leaky_relu(0.2)
        acc[j] = x;
        ss = fmaf(x, x, ss);
    }
    // reduce sumsq across the 8 threads (contiguous aligned lanes) of this row
    ss += __shfl_xor_sync(0xffffffffu, ss, 1);
    ss += __shfl_xor_sync(0xffffffffu, ss, 2);
    ss += __shfl_xor_sync(0xffffffffu, ss, 4);
    float inv = 1.0f / fmaxf(sqrtf(ss), 1e-12f);

    size_t node = (size_t)(r0 + r);
    float* pe  = &g_ego [node * DD + j0];
    float* pa  = &g_alle[node * 256 + (size_t)(layer + 1) * 64 + j0];
    float* psd = &g_side[node * DD + j0];
    #pragma unroll
    for (int j = 0; j < 8; j++) {
        pe[j]  = acc[j];
        pa[j]  = acc[j] * inv;
        psd[j] = 0.f;            // reset side for the next layer's SpMM
    }
}

// ---------------- predict: warp per batch element -------------------------
__global__ void k_pred(const int* __restrict__ users, const int* __restrict__ items,
                       const float* __restrict__ pW, const float* __restrict__ pb,
                       float* __restrict__ out) {
    int w = (blockIdx.x * blockDim.x + threadIdx.x) >> 5;
    if (w >= BB) return;
    int lane = threadIdx.x & 31;
    size_t u = (size_t)users[w];
    size_t v = (size_t)N_USER + (size_t)items[w];
    const float* pu = &g_alle[u * 256 + lane * 8];
    const float* pv = &g_alle[v * 256 + lane * 8];
    const float* pw = pW + lane * 8;
    float acc = 0.f;
    #pragma unroll
    for (int q = 0; q < 8; q++) acc = fmaf(pu[q] * pv[q], pw[q], acc);
    #pragma unroll
    for (int o = 16; o > 0; o >>= 1) acc += __shfl_xor_sync(0xffffffffu, acc, o);
    if (lane == 0) out[w] = 1.0f / (1.0f + expf(-(acc + pb[0])));
}

// ---------------- launch ---------------------------------------------------
extern "C" void kernel_launch(void* const* d_in, const int* in_sizes, int n_in,
                              void* d_out, int out_size) {
    const int*   users = (const int*)  d_in[0];
    const int*   items = (const int*)  d_in[1];
    const int*   arows = (const int*)  d_in[2];
    const int*   acols = (const int*)  d_in[3];
    const float* avals = (const float*)d_in[4];
    const float* ue    = (const float*)d_in[5];
    const float* ie    = (const float*)d_in[6];
    const float* Wg    = (const float*)d_in[7];
    const float* bg    = (const float*)d_in[8];
    const float* Wb    = (const float*)d_in[9];
    const float* bb    = (const float*)d_in[10];
    const float* pW    = (const float*)d_in[11];
    const float* pb    = (const float*)d_in[12];
    float* out = (float*)d_out;

    k_init<<<(NN * DD + 255) / 256, 256>>>(ue, ie);
    k_hist<<<(NNZ_E + 255) / 256, 256>>>(arows);
    k_scan<<<1, 1024>>>();
    k_fill<<<(NNZ_E + 255) / 256, 256>>>(arows, acols, avals);

    for (int k = 0; k < 3; k++) {
        k_spmm<<<NN / 8, 256>>>();            // warp per row, 8 warps/block
        k_transform<<<NN / 32, 256>>>(Wg, bg, Wb, bb, k);
    }

    k_pred<<<(BB * 32) / 256, 256>>>(users, items, pW, pb, out);
}

// round 3
// speedup vs baseline: 1.5631x; 1.5631x over previous
#include <cuda_runtime.h>
#include <cuda_bf16.h>
#include <math.h>

#define N_USER 100000
#define N_ITEM 60000
#define NN     160000      // total nodes
#define NNZ_E  2000000
#define BB     16384
#define DD     64

// ---------------- device scratch (static, allocation-free) ----------------
__device__ float g_ego [(size_t)NN * DD];        // 41 MB
__device__ float g_side[(size_t)NN * DD];        // 41 MB
__device__ float g_alle[(size_t)NN * 4 * DD];    // 164 MB  [node][256]
__device__ int   g_cnt   [NN];
__device__ int   g_off   [NN + 1];
__device__ int   g_cursor[NN];
__device__ int   g_ccol  [NNZ_E];
__device__ float g_cval  [NNZ_E];

// ---------------- init: ego = concat(user,item); alle slot0; zero cnt ------
__global__ void k_init(const float* __restrict__ ue, const float* __restrict__ ie) {
    int idx = blockIdx.x * blockDim.x + threadIdx.x;
    if (idx < NN * DD / 4) {
        int fidx = idx << 2;
        int node = fidx >> 6;
        int d    = fidx & 63;
        float4 v = (node < N_USER) ? ((const float4*)ue)[idx]
                                   : *(const float4*)&ie[fidx - N_USER * DD];
        *(float4*)&g_ego[fidx] = v;
        *(float4*)&g_alle[(size_t)node * 256 + d] = v;
    }
    if (idx < NN) g_cnt[idx] = 0;
}

// ---------------- CSR build ----------------
__global__ void k_hist(const int* __restrict__ rows) {
    int e = blockIdx.x * blockDim.x + threadIdx.x;
    if (e < NNZ_E) atomicAdd(&g_cnt[rows[e]], 1);
}

// single-block exclusive scan over g_cnt -> g_off, g_cursor
__global__ void k_scan() {
    const int CH = (NN + 1023) >> 10;   // 157
    int t = threadIdx.x;
    int b0 = t * CH;
    int b1 = b0 + CH; if (b1 > NN) b1 = NN;
    if (b0 > NN) b0 = NN;

    int s = 0;
    for (int i = b0; i < b1; i++) s += g_cnt[i];

    __shared__ int wsum[32];
    int lane = t & 31, wid = t >> 5;
    int v = s;
    #pragma unroll
    for (int o = 1; o < 32; o <<= 1) {
        int u = __shfl_up_sync(0xffffffffu, v, o);
        if (lane >= o) v += u;
    }
    if (lane == 31) wsum[wid] = v;
    __syncthreads();
    if (wid == 0) {
        int w = wsum[lane];
        #pragma unroll
        for (int o = 1; o < 32; o <<= 1) {
            int u = __shfl_up_sync(0xffffffffu, w, o);
            if (lane >= o) w += u;
        }
        wsum[lane] = w;  // inclusive warp sums
    }
    __syncthreads();
    int excl = v - s + (wid > 0 ? wsum[wid - 1] : 0);
    int off = excl;
    for (int i = b0; i < b1; i++) {
        g_off[i] = off;
        g_cursor[i] = off;
        off += g_cnt[i];
    }
    if (t == 1023) g_off[NN] = off;   // == NNZ_E
}

__global__ void k_fill(const int* __restrict__ rows, const int* __restrict__ cols,
                       const float* __restrict__ vals) {
    int e = blockIdx.x * blockDim.x + threadIdx.x;
    if (e < NNZ_E) {
        int r = rows[e];
        int p = atomicAdd(&g_cursor[r], 1);
        g_ccol[p] = cols[e];
        g_cval[p] = vals[e];
    }
}

// ---------------- SpMM: warp per row, 2 edges in flight (half-warps) -------
// side[r] = sum_e val*ego[col].  16 lanes x float4 cover one ego row (256B).
__global__ void k_spmm() {
    int w = (blockIdx.x * blockDim.x + threadIdx.x) >> 5;
    if (w >= NN) return;
    int lane = threadIdx.x & 31;
    int half = lane >> 4;          // which edge of the pair
    int q4   = (lane & 15) << 2;   // float4 column offset
    int s = g_off[w], e = g_off[w + 1];
    float ax = 0.f, ay = 0.f, az = 0.f, aw = 0.f;
    for (int base = s; base < e; base += 32) {
        int idx = base + lane;
        int c = 0; float v = 0.f;
        if (idx < e) { c = g_ccol[idx]; v = g_cval[idx]; }
        int m = e - base; if (m > 32) m = 32;
        int kk = (m + 1) >> 1;
        for (int k = 0; k < kk; k++) {
            int src = 2 * k + half;            // v==0 beyond m: contributes 0
            int   cc = __shfl_sync(0xffffffffu, c, src);
            float vv = __shfl_sync(0xffffffffu, v, src);
            float4 g = *(const float4*)&g_ego[(size_t)cc * DD + q4];
            ax = fmaf(vv, g.x, ax);
            ay = fmaf(vv, g.y, ay);
            az = fmaf(vv, g.z, az);
            aw = fmaf(vv, g.w, aw);
        }
    }
    // combine the two half-warp partials
    ax += __shfl_xor_sync(0xffffffffu, ax, 16);
    ay += __shfl_xor_sync(0xffffffffu, ay, 16);
    az += __shfl_xor_sync(0xffffffffu, az, 16);
    aw += __shfl_xor_sync(0xffffffffu, aw, 16);
    if (half == 0) {
        float4 o; o.x = ax; o.y = ay; o.z = az; o.w = aw;
        *(float4*)&g_side[(size_t)w * DD + q4] = o;
    }
}

// ---------------- transform: warp-uniform W, lane = row ---------------------
// block = 256 thr = 8 warps; block covers 64 rows. warp w: rows (w>>2)*32+lane,
// cols (w&3)*16. W address is uniform across the warp -> broadcast L1 load.
__global__ void k_transform(const float* __restrict__ Wg, const float* __restrict__ bg,
                            const float* __restrict__ Wb, const float* __restrict__ bb,
                            int layer) {
    __shared__ float sS[64][65];
    __shared__ float sE[64][65];
    __shared__ float sP[4][64];
    __shared__ float sInv[64];
    int r0 = blockIdx.x * 64;
    int t = threadIdx.x;
    int w = t >> 5, lane = t & 31;

    // load tiles (float4 global, scalar smem stores to keep [65] padding)
    for (int i = t; i < 1024; i += 256) {
        int rr = i >> 4, c4 = (i & 15) << 2;
        float4 a = *(const float4*)&g_side[(size_t)(r0 + rr) * DD + c4];
        float4 b = *(const float4*)&g_ego [(size_t)(r0 + rr) * DD + c4];
        sS[rr][c4] = a.x; sS[rr][c4+1] = a.y; sS[rr][c4+2] = a.z; sS[rr][c4+3] = a.w;
        sE[rr][c4] = b.x; sE[rr][c4+1] = b.y; sE[rr][c4+2] = b.z; sE[rr][c4+3] = b.w;
    }
    __syncthreads();

    int rg  = w >> 2;
    int cg  = w & 3;
    int row = rg * 32 + lane;
    int j0  = cg * 16;
    const float* wg = Wg + layer * 4096 + j0;
    const float* wb = Wb + layer * 4096 + j0;

    float acc[16];
    #pragma unroll
    for (int j = 0; j < 16; j++)
        acc[j] = bg[layer * 64 + j0 + j] + bb[layer * 64 + j0 + j];

    #pragma unroll 4
    for (int i = 0; i < 64; i++) {
        float si = sS[row][i];
        float bi = sE[row][i] * si;
        const float4* pg = (const float4*)(wg + i * 64);
        const float4* pb = (const float4*)(wb + i * 64);
        #pragma unroll
        for (int v = 0; v < 4; v++) {
            float4 a = pg[v], b = pb[v];
            acc[4*v+0] = fmaf(si, a.x, fmaf(bi, b.x, acc[4*v+0]));
            acc[4*v+1] = fmaf(si, a.y, fmaf(bi, b.y, acc[4*v+1]));
            acc[4*v+2] = fmaf(si, a.z, fmaf(bi, b.z, acc[4*v+2]));
            acc[4*v+3] = fmaf(si, a.w, fmaf(bi, b.w, acc[4*v+3]));
        }
    }

    float ss = 0.f;
    #pragma unroll
    for (int j = 0; j < 16; j++) {
        float x = acc[j];
        x = (x > 0.f) ? x : 0.2f * x;     // leaky_relu(0.2)
        acc[j] = x;
        ss = fmaf(x, x, ss);
    }
    sP[cg][row] = ss;
    __syncthreads();                       // all reads of sS/sE complete here

    if (t < 64) {
        float tot = sP[0][t] + sP[1][t] + sP[2][t] + sP[3][t];
        sInv[t] = 1.0f / fmaxf(sqrtf(tot), 1e-12f);
    }
    // stash activations into sE for coalesced writeback
    #pragma unroll
    for (int j = 0; j < 16; j++) sE[row][j0 + j] = acc[j];
    __syncthreads();

    for (int i = t; i < 1024; i += 256) {
        int rr = i >> 4, c4 = (i & 15) << 2;
        float inv = sInv[rr];
        float4 o;
        o.x = sE[rr][c4]; o.y = sE[rr][c4+1]; o.z = sE[rr][c4+2]; o.w = sE[rr][c4+3];
        *(float4*)&g_ego[(size_t)(r0 + rr) * DD + c4] = o;
        float4 n; n.x = o.x*inv; n.y = o.y*inv; n.z = o.z*inv; n.w = o.w*inv;
        *(float4*)&g_alle[(size_t)(r0 + rr) * 256 + (size_t)(layer + 1) * 64 + c4] = n;
    }
}

// ---------------- predict: warp per batch element -------------------------
__global__ void k_pred(const int* __restrict__ users, const int* __restrict__ items,
                       const float* __restrict__ pW, const float* __restrict__ pb,
                       float* __restrict__ out) {
    int w = (blockIdx.x * blockDim.x + threadIdx.x) >> 5;
    if (w >= BB) return;
    int lane = threadIdx.x & 31;
    size_t u = (size_t)users[w];
    size_t v = (size_t)N_USER + (size_t)items[w];
    const float* pu = &g_alle[u * 256 + lane * 8];
    const float* pv = &g_alle[v * 256 + lane * 8];
    const float* pw = pW + lane * 8;
    float acc = 0.f;
    #pragma unroll
    for (int q = 0; q < 8; q++) acc = fmaf(pu[q] * pv[q], pw[q], acc);
    #pragma unroll
    for (int o = 16; o > 0; o >>= 1) acc += __shfl_xor_sync(0xffffffffu, acc, o);
    if (lane == 0) out[w] = 1.0f / (1.0f + expf(-(acc + pb[0])));
}

// ---------------- launch ---------------------------------------------------
extern "C" void kernel_launch(void* const* d_in, const int* in_sizes, int n_in,
                              void* d_out, int out_size) {
    const int*   users = (const int*)  d_in[0];
    const int*   items = (const int*)  d_in[1];
    const int*   arows = (const int*)  d_in[2];
    const int*   acols = (const int*)  d_in[3];
    const float* avals = (const float*)d_in[4];
    const float* ue    = (const float*)d_in[5];
    const float* ie    = (const float*)d_in[6];
    const float* Wg    = (const float*)d_in[7];
    const float* bg    = (const float*)d_in[8];
    const float* Wb    = (const float*)d_in[9];
    const float* bb    = (const float*)d_in[10];
    const float* pW    = (const float*)d_in[11];
    const float* pb    = (const float*)d_in[12];
    float* out = (float*)d_out;

    k_init<<<(NN * DD / 4 + 255) / 256, 256>>>(ue, ie);
    k_hist<<<(NNZ_E + 255) / 256, 256>>>(arows);
    k_scan<<<1, 1024>>>();
    k_fill<<<(NNZ_E + 255) / 256, 256>>>(arows, acols, avals);

    for (int k = 0; k < 3; k++) {
        k_spmm<<<NN / 8, 256>>>();                 // warp per row
        k_transform<<<NN / 64, 256>>>(Wg, bg, Wb, bb, k);
    }

    k_pred<<<(BB * 32) / 256, 256>>>(users, items, pW, pb, out);
}

// round 4
// speedup vs baseline: 2.3916x; 1.5300x over previous
#include <cuda_runtime.h>
#include <cuda_bf16.h>
#include <math.h>

#define N_USER 100000
#define N_ITEM 60000
#define NN     160000      // total nodes
#define NNZ_E  2000000
#define BB     16384
#define DD     64

typedef unsigned long long u64;

// ---------------- device scratch (static, allocation-free) ----------------
__device__ float g_ego [(size_t)NN * DD];        // 41 MB
__device__ float g_side[(size_t)NN * DD];        // 41 MB
__device__ float g_alle[(size_t)NN * 4 * DD];    // 164 MB  [node][256]
__device__ int   g_cnt   [NN];
__device__ int   g_off   [NN + 1];
__device__ int   g_cursor[NN];
__device__ int2  g_cv    [NNZ_E];                // packed (col, val-bits)

// ---------------- f32x2 packed helpers -------------------------------------
__device__ __forceinline__ u64 pack2(float x, float y) {
    u64 r;
    asm("mov.b64 %0, {%1, %2};" : "=l"(r) : "f"(x), "f"(y));
    return r;
}
__device__ __forceinline__ float2 unpack2(u64 v) {
    float2 r;
    asm("mov.b64 {%0, %1}, %2;" : "=f"(r.x), "=f"(r.y) : "l"(v));
    return r;
}
__device__ __forceinline__ void ffma2(u64& d, u64 a, u64 b) {
    asm("fma.rn.f32x2 %0, %1, %2, %0;" : "+l"(d) : "l"(a), "l"(b));
}

// ---------------- init: ego = concat(user,item); alle slot0; zero cnt ------
__global__ void k_init(const float* __restrict__ ue, const float* __restrict__ ie) {
    int idx = blockIdx.x * blockDim.x + threadIdx.x;
    if (idx < NN * DD / 4) {
        int fidx = idx << 2;
        int node = fidx >> 6;
        int d    = fidx & 63;
        float4 v = (node < N_USER) ? ((const float4*)ue)[idx]
                                   : *(const float4*)&ie[fidx - N_USER * DD];
        *(float4*)&g_ego[fidx] = v;
        *(float4*)&g_alle[(size_t)node * 256 + d] = v;
    }
    if (idx < NN) g_cnt[idx] = 0;
}

// ---------------- CSR build ----------------
__global__ void k_hist(const int* __restrict__ rows) {
    int e = blockIdx.x * blockDim.x + threadIdx.x;
    if (e < NNZ_E) atomicAdd(&g_cnt[rows[e]], 1);
}

// single-block exclusive scan over g_cnt -> g_off, g_cursor
__global__ void k_scan() {
    const int CH = (NN + 1023) >> 10;   // 157
    int t = threadIdx.x;
    int b0 = t * CH;
    int b1 = b0 + CH; if (b1 > NN) b1 = NN;
    if (b0 > NN) b0 = NN;

    int s = 0;
    for (int i = b0; i < b1; i++) s += g_cnt[i];

    __shared__ int wsum[32];
    int lane = t & 31, wid = t >> 5;
    int v = s;
    #pragma unroll
    for (int o = 1; o < 32; o <<= 1) {
        int u = __shfl_up_sync(0xffffffffu, v, o);
        if (lane >= o) v += u;
    }
    if (lane == 31) wsum[wid] = v;
    __syncthreads();
    if (wid == 0) {
        int w = wsum[lane];
        #pragma unroll
        for (int o = 1; o < 32; o <<= 1) {
            int u = __shfl_up_sync(0xffffffffu, w, o);
            if (lane >= o) w += u;
        }
        wsum[lane] = w;  // inclusive warp sums
    }
    __syncthreads();
    int excl = v - s + (wid > 0 ? wsum[wid - 1] : 0);
    int off = excl;
    for (int i = b0; i < b1; i++) {
        g_off[i] = off;
        g_cursor[i] = off;
        off += g_cnt[i];
    }
    if (t == 1023) g_off[NN] = off;   // == NNZ_E
}

__global__ void k_fill(const int* __restrict__ rows, const int* __restrict__ cols,
                       const float* __restrict__ vals) {
    int e = blockIdx.x * blockDim.x + threadIdx.x;
    if (e < NNZ_E) {
        int r = rows[e];
        int p = atomicAdd(&g_cursor[r], 1);
        g_cv[p] = make_int2(cols[e], __float_as_int(vals[e]));
    }
}

// ---------------- SpMM: warp per row, half-warp per edge, no shuffles ------
// side[r] = sum_e val*ego[col].  16 lanes x float4 cover one ego row (256B).
__global__ void k_spmm() {
    int w = (blockIdx.x * blockDim.x + threadIdx.x) >> 5;
    if (w >= NN) return;
    int lane = threadIdx.x & 31;
    int half = lane >> 4;          // which edge of the pair
    int q4   = (lane & 15) << 2;   // float4 column offset
    int s = g_off[w], e = g_off[w + 1];
    u64 a01 = 0, a23 = 0;
    #pragma unroll 2
    for (int idx = s + half; idx < e; idx += 2) {
        int2 cv = g_cv[idx];                       // broadcast within half-warp
        float v = __int_as_float(cv.y);
        u64 v2 = pack2(v, v);
        const u64* pg = (const u64*)&g_ego[(size_t)cv.x * DD + q4];
        u64 g0 = pg[0], g1 = pg[1];
        ffma2(a01, v2, g0);
        ffma2(a23, v2, g1);
    }
    float2 p01 = unpack2(a01), p23 = unpack2(a23);
    float ax = p01.x, ay = p01.y, az = p23.x, aw = p23.y;
    ax += __shfl_xor_sync(0xffffffffu, ax, 16);
    ay += __shfl_xor_sync(0xffffffffu, ay, 16);
    az += __shfl_xor_sync(0xffffffffu, az, 16);
    aw += __shfl_xor_sync(0xffffffffu, aw, 16);
    if (half == 0) {
        float4 o; o.x = ax; o.y = ay; o.z = az; o.w = aw;
        *(float4*)&g_side[(size_t)w * DD + q4] = o;
    }
}

// ---------------- transform -------------------------------------------------
// block = 256 thr = 8 warps covers 128 rows. warp w: colgroup=(w&3)*16,
// rowhalf=(w>>2); lane owns rows rh*64+lane and rh*64+lane+32.
// W cached in shared (uniform LDS.128 broadcast). acc in packed f32x2.
// dynamic smem layout (floats):
//   sS [128][65], sE [128][65], sWg[4096], sWb[4096], sP[4][128], sInv[128]
#define TR_SMEM_FLOATS (128*65 + 128*65 + 4096 + 4096 + 4*128 + 128)
__global__ void k_transform(const float* __restrict__ Wg, const float* __restrict__ bg,
                            const float* __restrict__ Wb, const float* __restrict__ bb,
                            int layer) {
    extern __shared__ float smem[];
    float (*sS)[65] = (float(*)[65])smem;
    float (*sE)[65] = (float(*)[65])(smem + 128 * 65);
    float* sWg = smem + 2 * 128 * 65;
    float* sWb = sWg + 4096;
    float* sP  = sWb + 4096;        // [4][128]
    float* sInv = sP + 4 * 128;     // [128]

    int r0 = blockIdx.x * 128;
    int t = threadIdx.x;
    int w = t >> 5, lane = t & 31;

    // stage side/ego tiles (128 rows x 64 cols)
    for (int i = t; i < 2048; i += 256) {
        int rr = i >> 4, c4 = (i & 15) << 2;
        float4 a = *(const float4*)&g_side[(size_t)(r0 + rr) * DD + c4];
        float4 b = *(const float4*)&g_ego [(size_t)(r0 + rr) * DD + c4];
        sS[rr][c4] = a.x; sS[rr][c4+1] = a.y; sS[rr][c4+2] = a.z; sS[rr][c4+3] = a.w;
        sE[rr][c4] = b.x; sE[rr][c4+1] = b.y; sE[rr][c4+2] = b.z; sE[rr][c4+3] = b.w;
    }
    // stage W (two 64x64 matrices for this layer)
    for (int i = t; i < 1024; i += 256) {
        ((float4*)sWg)[i] = ((const float4*)(Wg + layer * 4096))[i];
        ((float4*)sWb)[i] = ((const float4*)(Wb + layer * 4096))[i];
    }
    __syncthreads();

    int cg = w & 3;
    int rh = w >> 2;
    int r1 = rh * 64 + lane;
    int r2 = r1 + 32;
    int j0 = cg * 16;

    u64 acc1[8], acc2[8];
    #pragma unroll
    for (int v = 0; v < 8; v++) {
        float bx = bg[layer * 64 + j0 + 2*v]     + bb[layer * 64 + j0 + 2*v];
        float by = bg[layer * 64 + j0 + 2*v + 1] + bb[layer * 64 + j0 + 2*v + 1];
        acc1[v] = pack2(bx, by);
        acc2[v] = acc1[v];
    }

    #pragma unroll 4
    for (int i = 0; i < 64; i++) {
        float s1 = sS[r1][i];
        float b1 = sE[r1][i] * s1;
        float s2 = sS[r2][i];
        float b2 = sE[r2][i] * s2;
        u64 s1p = pack2(s1, s1), b1p = pack2(b1, b1);
        u64 s2p = pack2(s2, s2), b2p = pack2(b2, b2);
        const u64* pg = (const u64*)&sWg[i * 64 + j0];   // 8 pairs (uniform addr)
        const u64* pb = (const u64*)&sWb[i * 64 + j0];
        #pragma unroll
        for (int v = 0; v < 8; v++) {
            u64 gg = pg[v], hh = pb[v];
            ffma2(acc1[v], s1p, gg); ffma2(acc1[v], b1p, hh);
            ffma2(acc2[v], s2p, gg); ffma2(acc2[v], b2p, hh);
        }
    }

    // leaky relu + per-row sumsq partials
    float av1[16], av2[16];
    float ss1 = 0.f, ss2 = 0.f;
    #pragma unroll
    for (int v = 0; v < 8; v++) {
        float2 x = unpack2(acc1[v]);
        x.x = (x.x > 0.f) ? x.x : 0.2f * x.x;
        x.y = (x.y > 0.f) ? x.y : 0.2f * x.y;
        av1[2*v] = x.x; av1[2*v+1] = x.y;
        ss1 = fmaf(x.x, x.x, fmaf(x.y, x.y, ss1));
        float2 y = unpack2(acc2[v]);
        y.x = (y.x > 0.f) ? y.x : 0.2f * y.x;
        y.y = (y.y > 0.f) ? y.y : 0.2f * y.y;
        av2[2*v] = y.x; av2[2*v+1] = y.y;
        ss2 = fmaf(y.x, y.x, fmaf(y.y, y.y, ss2));
    }
    sP[cg * 128 + r1] = ss1;
    sP[cg * 128 + r2] = ss2;
    __syncthreads();            // all reads of sS/sE and writes of sP done

    if (t < 128) {
        float tot = sP[t] + sP[128 + t] + sP[256 + t] + sP[384 + t];
        sInv[t] = 1.0f / fmaxf(sqrtf(tot), 1e-12f);
    }
    // stash activations into sE for coalesced writeback
    #pragma unroll
    for (int j = 0; j < 16; j++) {
        sE[r1][j0 + j] = av1[j];
        sE[r2][j0 + j] = av2[j];
    }
    __syncthreads();

    for (int i = t; i < 2048; i += 256) {
        int rr = i >> 4, c4 = (i & 15) << 2;
        float inv = sInv[rr];
        float4 o;
        o.x = sE[rr][c4]; o.y = sE[rr][c4+1]; o.z = sE[rr][c4+2]; o.w = sE[rr][c4+3];
        *(float4*)&g_ego[(size_t)(r0 + rr) * DD + c4] = o;
        float4 n; n.x = o.x*inv; n.y = o.y*inv; n.z = o.z*inv; n.w = o.w*inv;
        *(float4*)&g_alle[(size_t)(r0 + rr) * 256 + (size_t)(layer + 1) * 64 + c4] = n;
    }
}

// ---------------- predict: warp per batch element -------------------------
__global__ void k_pred(const int* __restrict__ users, const int* __restrict__ items,
                       const float* __restrict__ pW, const float* __restrict__ pb,
                       float* __restrict__ out) {
    int w = (blockIdx.x * blockDim.x + threadIdx.x) >> 5;
    if (w >= BB) return;
    int lane = threadIdx.x & 31;
    size_t u = (size_t)users[w];
    size_t v = (size_t)N_USER + (size_t)items[w];
    const float* pu = &g_alle[u * 256 + lane * 8];
    const float* pv = &g_alle[v * 256 + lane * 8];
    const float* pw = pW + lane * 8;
    float acc = 0.f;
    #pragma unroll
    for (int q = 0; q < 8; q++) acc = fmaf(pu[q] * pv[q], pw[q], acc);
    #pragma unroll
    for (int o = 16; o > 0; o >>= 1) acc += __shfl_xor_sync(0xffffffffu, acc, o);
    if (lane == 0) out[w] = 1.0f / (1.0f + expf(-(acc + pb[0])));
}

// ---------------- launch ---------------------------------------------------
extern "C" void kernel_launch(void* const* d_in, const int* in_sizes, int n_in,
                              void* d_out, int out_size) {
    const int*   users = (const int*)  d_in[0];
    const int*   items = (const int*)  d_in[1];
    const int*   arows = (const int*)  d_in[2];
    const int*   acols = (const int*)  d_in[3];
    const float* avals = (const float*)d_in[4];
    const float* ue    = (const float*)d_in[5];
    const float* ie    = (const float*)d_in[6];
    const float* Wg    = (const float*)d_in[7];
    const float* bg    = (const float*)d_in[8];
    const float* Wb    = (const float*)d_in[9];
    const float* bb    = (const float*)d_in[10];
    const float* pW    = (const float*)d_in[11];
    const float* pb    = (const float*)d_in[12];
    float* out = (float*)d_out;

    const int tr_smem = TR_SMEM_FLOATS * 4;   // ~99.5 KB
    cudaFuncSetAttribute(k_transform, cudaFuncAttributeMaxDynamicSharedMemorySize, tr_smem);

    k_init<<<(NN * DD / 4 + 255) / 256, 256>>>(ue, ie);
    k_hist<<<(NNZ_E + 255) / 256, 256>>>(arows);
    k_scan<<<1, 1024>>>();
    k_fill<<<(NNZ_E + 255) / 256, 256>>>(arows, acols, avals);

    for (int k = 0; k < 3; k++) {
        k_spmm<<<NN / 8, 256>>>();                        // warp per row
        k_transform<<<NN / 128, 256, tr_smem>>>(Wg, bg, Wb, bb, k);
    }

    k_pred<<<(BB * 32) / 256, 256>>>(users, items, pW, pb, out);
}